// round 7
// baseline (speedup 1.0000x reference)
#include <cuda_runtime.h>
#include <math_constants.h>

// cummax along T for [B, T, H, C] = [16, 512, 64, 128] fp32.
//
// R6: float4 vectorization of the R5 streaming column-scan.
//  - One thread per float4-column (4 consecutive c's): 32768 threads.
//  - LDG.128/STG.128: 4x fewer memory-op issues and address IMADs per byte;
//    4 independent max chains per thread (shorter recurrence).
//  - Block=32, grid=1024 -> 6.92 blocks/SM keeps the ~1% wave quantization
//    of R5 (block=64/grid=512 would regress to a 15% tail).
//  - UNROLL 8 float4 = 128 B in flight per thread; ~28 KB/SM aggregate,
//    comfortably above the ~6 KB Little's-law requirement.

#define B_DIM 16
#define T_DIM 512
#define HC_DIM (64 * 128)            // 8192 floats per timestep
#define HC4 (HC_DIM / 4)             // 2048 float4 per timestep
#define UNROLL 8

__global__ __launch_bounds__(32)
void cummax_time_kernel_v4(const float4* __restrict__ in, float4* __restrict__ out) {
    const unsigned col4 = blockIdx.x * blockDim.x + threadIdx.x;   // 0 .. B*HC4-1, exact

    const unsigned b      = col4 / HC4;
    const unsigned inner4 = col4 % HC4;

    const size_t base = (size_t)b * T_DIM * HC4 + inner4;
    const float4* __restrict__ p = in + base;
    float4* __restrict__       q = out + base;

    float mx = -CUDART_INF_F;
    float my = -CUDART_INF_F;
    float mz = -CUDART_INF_F;
    float mw = -CUDART_INF_F;

    #pragma unroll 1
    for (int tt = 0; tt < T_DIM; tt += UNROLL) {
        float4 v[UNROLL];
        #pragma unroll
        for (int i = 0; i < UNROLL; ++i) {
            v[i] = __ldcs(p + (size_t)i * HC4);      // streaming LDG.128
        }
        #pragma unroll
        for (int i = 0; i < UNROLL; ++i) {
            mx = fmaxf(mx, v[i].x);  v[i].x = mx;
            my = fmaxf(my, v[i].y);  v[i].y = my;
            mz = fmaxf(mz, v[i].z);  v[i].z = mz;
            mw = fmaxf(mw, v[i].w);  v[i].w = mw;
        }
        #pragma unroll
        for (int i = 0; i < UNROLL; ++i) {
            __stcs(q + (size_t)i * HC4, v[i]);       // streaming STG.128
        }
        p += (size_t)UNROLL * HC4;
        q += (size_t)UNROLL * HC4;
    }
}

extern "C" void kernel_launch(void* const* d_in, const int* in_sizes, int n_in,
                              void* d_out, int out_size) {
    const float4* in = (const float4*)d_in[0];
    float4* out = (float4*)d_out;

    const int total_cols4 = B_DIM * HC4;              // 32768
    const int threads = 32;
    const int blocks = total_cols4 / threads;         // 1024, exact -> 6.92/SM

    cummax_time_kernel_v4<<<blocks, threads>>>(in, out);
}

// round 9
// speedup vs baseline: 1.1180x; 1.1180x over previous
#include <cuda_runtime.h>
#include <math_constants.h>

// cummax along T for [B, T, H, C] = [16, 512, 64, 128] fp32.
//
// R7 = R6 float4 structure + R5's winning in-flight depth.
// Post-mortem constant: this stream needs ~50+ KB/SM of outstanding loads.
//   R5  scalar UNROLL=16: 55 KB/SM -> DRAM 77%  (79.6us)
//   R6  float4 UNROLL=8 : 28 KB/SM -> DRAM 67%  (91.4us)
//   R7  float4 UNROLL=16: 56 KB/SM -> predict 80%+
// Keeps: 1024 blocks (6.92/SM wave balance), streaming ld/st, immediate
// offsets off an incremented base pointer, 4 independent max chains/thread.

#define B_DIM 16
#define T_DIM 512
#define HC_DIM (64 * 128)            // 8192 floats per timestep
#define HC4 (HC_DIM / 4)             // 2048 float4 per timestep
#define UNROLL 16

__global__ __launch_bounds__(32)
void cummax_time_kernel_v4(const float4* __restrict__ in, float4* __restrict__ out) {
    const unsigned col4 = blockIdx.x * blockDim.x + threadIdx.x;   // 0 .. B*HC4-1, exact

    const unsigned b      = col4 / HC4;
    const unsigned inner4 = col4 % HC4;

    const size_t base = (size_t)b * T_DIM * HC4 + inner4;
    const float4* __restrict__ p = in + base;
    float4* __restrict__       q = out + base;

    float mx = -CUDART_INF_F;
    float my = -CUDART_INF_F;
    float mz = -CUDART_INF_F;
    float mw = -CUDART_INF_F;

    // 32 outer iterations; 16 independent LDG.128 front-batched (256 B/thread
    // in flight), then 4 independent serial max chains, then 16 STG.128.
    #pragma unroll 1
    for (int tt = 0; tt < T_DIM; tt += UNROLL) {
        float4 v[UNROLL];
        #pragma unroll
        for (int i = 0; i < UNROLL; ++i) {
            v[i] = __ldcs(p + (size_t)i * HC4);      // streaming LDG.128
        }
        #pragma unroll
        for (int i = 0; i < UNROLL; ++i) {
            mx = fmaxf(mx, v[i].x);  v[i].x = mx;
            my = fmaxf(my, v[i].y);  v[i].y = my;
            mz = fmaxf(mz, v[i].z);  v[i].z = mz;
            mw = fmaxf(mw, v[i].w);  v[i].w = mw;
        }
        #pragma unroll
        for (int i = 0; i < UNROLL; ++i) {
            __stcs(q + (size_t)i * HC4, v[i]);       // streaming STG.128
        }
        p += (size_t)UNROLL * HC4;
        q += (size_t)UNROLL * HC4;
    }
}

extern "C" void kernel_launch(void* const* d_in, const int* in_sizes, int n_in,
                              void* d_out, int out_size) {
    const float4* in = (const float4*)d_in[0];
    float4* out = (float4*)d_out;

    const int total_cols4 = B_DIM * HC4;              // 32768
    const int threads = 32;
    const int blocks = total_cols4 / threads;         // 1024, exact -> 6.92/SM

    cummax_time_kernel_v4<<<blocks, threads>>>(in, out);
}